// round 4
// baseline (speedup 1.0000x reference)
#include <cuda_runtime.h>
#include <math.h>
#include <stdint.h>

#define Bz 2
#define Sz 2048
#define Dz 1024
#define Hz 16
#define HDz 64

// ---------------- scratch (device globals; no allocation allowed) ----------
__device__ float g_ln[Bz * Sz * Dz];            // layernorm output (reused)
__device__ float g_q[Bz * Hz * Sz * HDz];       // q in [B,H,S,hd]
__device__ float g_a[Bz * Sz * Dz];             // attention output in [B,S,D]
__device__ float g_xa[Bz * Sz * Dz];            // x + attn
__device__ float g_h1[Bz * Sz * 4 * Dz];        // mlp hidden

// ---------------- helpers ---------------------------------------------------
__device__ __forceinline__ uint32_t f2tf32(float x) {
    uint32_t y;
    asm("cvt.rna.tf32.f32 %0, %1;" : "=r"(y) : "f"(x));
    return y;
}
__device__ __forceinline__ float tfr(float x) { return __uint_as_float(f2tf32(x)); }

__device__ __forceinline__ void mma_tf32(float (&d)[4], const uint32_t (&a)[4], const uint32_t (&b)[2]) {
    asm volatile("mma.sync.aligned.m16n8k8.row.col.f32.tf32.tf32.f32 "
                 "{%0,%1,%2,%3}, {%4,%5,%6,%7}, {%8,%9}, {%0,%1,%2,%3};"
                 : "+f"(d[0]), "+f"(d[1]), "+f"(d[2]), "+f"(d[3])
                 : "r"(a[0]), "r"(a[1]), "r"(a[2]), "r"(a[3]), "r"(b[0]), "r"(b[1]));
}

// fast exp on the FMA pipe: e^x for x <= ~10; deg-5 Taylor of 2^f, rel err ~1.5e-4
__device__ __forceinline__ float fexp(float x) {
    float y = fmaxf(x * 1.4426950408889634f, -126.0f);
    float n = floorf(y);
    float f = y - n;
    float p = fmaf(f, 0.0013333558f, 0.0096181291f);
    p = fmaf(f, p, 0.0555041087f);
    p = fmaf(f, p, 0.2402265069f);
    p = fmaf(f, p, 0.6931471806f);
    p = fmaf(f, p, 1.0f);
    float sc = __int_as_float(((int)n + 127) << 23);
    return p * sc;
}

// ---------------- layernorm: one block per row, D=1024 ---------------------
__global__ void layernorm_k(const float* __restrict__ x, const float* __restrict__ g,
                            const float* __restrict__ b, float* __restrict__ y) {
    int row = blockIdx.x;
    int tid = threadIdx.x;                       // 256 threads
    const float4* xr = (const float4*)(x + (size_t)row * Dz);
    float4 v = xr[tid];
    float s  = v.x + v.y + v.z + v.w;
    float sq = v.x * v.x + v.y * v.y + v.z * v.z + v.w * v.w;

    __shared__ float shs[8], shq[8];
    for (int o = 16; o; o >>= 1) { s += __shfl_xor_sync(0xffffffffu, s, o); sq += __shfl_xor_sync(0xffffffffu, sq, o); }
    int lane = tid & 31, wid = tid >> 5;
    if (lane == 0) { shs[wid] = s; shq[wid] = sq; }
    __syncthreads();
    float ts = 0.f, tq = 0.f;
    #pragma unroll
    for (int i = 0; i < 8; i++) { ts += shs[i]; tq += shq[i]; }
    float mean = ts * (1.0f / Dz);
    float var  = tq * (1.0f / Dz) - mean * mean;
    float rstd = rsqrtf(var + 1e-5f);

    float4 gg = ((const float4*)g)[tid];
    float4 bb = ((const float4*)b)[tid];
    float4 o;
    o.x = (v.x - mean) * rstd * gg.x + bb.x;
    o.y = (v.y - mean) * rstd * gg.y + bb.y;
    o.z = (v.z - mean) * rstd * gg.z + bb.z;
    o.w = (v.w - mean) * rstd * gg.w + bb.w;
    ((float4*)(y + (size_t)row * Dz))[tid] = o;
}

// ---------------- tf32 tensor-core GEMM ------------------------------------
__device__ __forceinline__ void wqkv(float* __restrict__ q, float* __restrict__ pres,
                                     int r, int c, float v) {
    int b = r >> 11, s = r & (Sz - 1);
    int which = c >> 10, rest = c & (Dz - 1);
    int h = rest >> 6, d = rest & 63;
    if (which == 0)
        q[(((size_t)(b * Hz + h) * Sz + s) * HDz) + d] = v;
    else
        pres[(((size_t)((b * 2 + (which - 1)) * Hz + h) * Sz + s) * HDz) + d] = v;
}

template <int EPI>  // 0 bias, 1 bias+res, 2 bias+gelu, 3 bias+scatter qkv
__global__ __launch_bounds__(256)
void tf32gemm(const float* __restrict__ A, const float* __restrict__ B,
              const float* __restrict__ bias, const float* __restrict__ res,
              float* __restrict__ C, float* __restrict__ qp, float* __restrict__ pp,
              int M, int N, int K, int lda, int ldb, int ldc) {
    __shared__ float As[128][36];
    __shared__ float Bs[32][132];

    int tid = threadIdx.x;
    int row0 = blockIdx.y * 128, col0 = blockIdx.x * 128;

    int arow = tid >> 3;
    int acol = (tid & 7) * 4;
    int brow = tid >> 5;
    int bcol = (tid & 31) * 4;

    int lane = tid & 31, wid = tid >> 5;
    int wm = (wid >> 2) * 64, wn = (wid & 3) * 32;
    int g = lane >> 2, t = lane & 3;

    float acc[16][4];
    #pragma unroll
    for (int i = 0; i < 16; i++)
        #pragma unroll
        for (int j = 0; j < 4; j++) acc[i][j] = 0.f;

    float4 ra[4], rb[4];
    #pragma unroll
    for (int i = 0; i < 4; i++)
        ra[i] = *(const float4*)(A + (size_t)(row0 + arow + i * 32) * lda + acol);
    #pragma unroll
    for (int p = 0; p < 4; p++)
        rb[p] = *(const float4*)(B + (size_t)(brow + p * 8) * ldb + col0 + bcol);

    for (int k0 = 0; k0 < K; k0 += 32) {
        #pragma unroll
        for (int i = 0; i < 4; i++) {
            As[arow + i * 32][acol + 0] = tfr(ra[i].x);
            As[arow + i * 32][acol + 1] = tfr(ra[i].y);
            As[arow + i * 32][acol + 2] = tfr(ra[i].z);
            As[arow + i * 32][acol + 3] = tfr(ra[i].w);
        }
        #pragma unroll
        for (int p = 0; p < 4; p++) {
            Bs[brow + p * 8][bcol + 0] = tfr(rb[p].x);
            Bs[brow + p * 8][bcol + 1] = tfr(rb[p].y);
            Bs[brow + p * 8][bcol + 2] = tfr(rb[p].z);
            Bs[brow + p * 8][bcol + 3] = tfr(rb[p].w);
        }
        __syncthreads();

        if (k0 + 32 < K) {
            #pragma unroll
            for (int i = 0; i < 4; i++)
                ra[i] = *(const float4*)(A + (size_t)(row0 + arow + i * 32) * lda + k0 + 32 + acol);
            #pragma unroll
            for (int p = 0; p < 4; p++)
                rb[p] = *(const float4*)(B + (size_t)(k0 + 32 + brow + p * 8) * ldb + col0 + bcol);
        }

        #pragma unroll
        for (int ks = 0; ks < 4; ks++) {
            int k = ks * 8;
            uint32_t afr[4][4], bfr[4][2];
            #pragma unroll
            for (int mi = 0; mi < 4; mi++) {
                int r = wm + mi * 16 + g;
                afr[mi][0] = __float_as_uint(As[r][k + t]);
                afr[mi][1] = __float_as_uint(As[r + 8][k + t]);
                afr[mi][2] = __float_as_uint(As[r][k + t + 4]);
                afr[mi][3] = __float_as_uint(As[r + 8][k + t + 4]);
            }
            #pragma unroll
            for (int ni = 0; ni < 4; ni++) {
                int c = wn + ni * 8 + g;
                bfr[ni][0] = __float_as_uint(Bs[k + t][c]);
                bfr[ni][1] = __float_as_uint(Bs[k + t + 4][c]);
            }
            #pragma unroll
            for (int mi = 0; mi < 4; mi++)
                #pragma unroll
                for (int ni = 0; ni < 4; ni++)
                    mma_tf32(acc[mi * 4 + ni], afr[mi], bfr[ni]);
        }
        __syncthreads();
    }

    #pragma unroll
    for (int mi = 0; mi < 4; mi++) {
        #pragma unroll
        for (int ni = 0; ni < 4; ni++) {
            int r = row0 + wm + mi * 16 + g;
            int c = col0 + wn + ni * 8 + t * 2;
            float b0 = bias[c], b1 = bias[c + 1];
            float v0 = acc[mi * 4 + ni][0] + b0;
            float v1 = acc[mi * 4 + ni][1] + b1;
            float v2 = acc[mi * 4 + ni][2] + b0;
            float v3 = acc[mi * 4 + ni][3] + b1;
            if (EPI == 1) {
                v0 += res[(size_t)r * ldc + c];
                v1 += res[(size_t)r * ldc + c + 1];
                v2 += res[(size_t)(r + 8) * ldc + c];
                v3 += res[(size_t)(r + 8) * ldc + c + 1];
            }
            if (EPI == 2) {
                v0 = 0.5f * v0 * (1.0f + erff(v0 * 0.70710678118654752f));
                v1 = 0.5f * v1 * (1.0f + erff(v1 * 0.70710678118654752f));
                v2 = 0.5f * v2 * (1.0f + erff(v2 * 0.70710678118654752f));
                v3 = 0.5f * v3 * (1.0f + erff(v3 * 0.70710678118654752f));
            }
            if (EPI == 3) {
                wqkv(qp, pp, r, c, v0);
                wqkv(qp, pp, r, c + 1, v1);
                wqkv(qp, pp, r + 8, c, v2);
                wqkv(qp, pp, r + 8, c + 1, v3);
            } else {
                *(float2*)(C + (size_t)r * ldc + c) = make_float2(v0, v1);
                *(float2*)(C + (size_t)(r + 8) * ldc + c) = make_float2(v2, v3);
            }
        }
    }
}

// ---------------- fused attention: scores + softmax + A=P@V ----------------
// One block per (128-row block, bh). Pass 1: online row max/sum (MMA, no
// score materialization). Pass 2: recompute scores, write normalized w once,
// accumulate A += P@V via MMA through smem.
#define SQ(r, c) sQ[(r) * 68 + (c)]
#define SK(d, j) sK[(d) * 133 + (j)]
#define SV(k, n) sV[(k) * 68 + (n)]
#define SP(r, c) sP[(r) * 132 + (c)]

__global__ __launch_bounds__(256, 1)
void attn_fused(const float* __restrict__ q, const float* __restrict__ present,
                float* __restrict__ w, float* __restrict__ a) {
    int rb = (int)gridDim.y - 1 - (int)blockIdx.y;   // heavy blocks first
    int row0 = rb * 128;
    int bh = blockIdx.z;
    int b = bh >> 4, h = bh & 15;
    const float* Q  = q + (size_t)bh * Sz * HDz;
    const float* Kd = present + (size_t)((b * 2) * Hz + h) * Sz * HDz;
    const float* Vd = present + (size_t)((b * 2 + 1) * Hz + h) * Sz * HDz;
    float* W = w + (size_t)bh * Sz * Sz;

    extern __shared__ float sm[];
    float* sQ    = sm;                    // 128*68
    float* sK    = sQ + 128 * 68;         // 64*133
    float* sV    = sK + 64 * 133;         // 128*68
    float* sP    = sV + 128 * 68;         // 128*132
    float* sMrun = sP + 128 * 132;        // 128
    float* sLrun = sMrun + 128;           // 128
    float* sLinv = sLrun + 128;           // 128
    float* sScl  = sLinv + 128;           // 128
    float* sRedM = sScl + 128;            // 4*128
    float* sRedL = sRedM + 512;           // 4*128

    int tid = threadIdx.x;
    int lane = tid & 31, wid = tid >> 5;
    int g = lane >> 2, t = lane & 3;
    int wm = (wid >> 2) * 64, wn = (wid & 3) * 32, wnI = wid & 3;
    int ldr = tid >> 4, ldc4 = (tid & 15) * 4;

    // load Q tile (tf32-rounded)
    #pragma unroll
    for (int i = 0; i < 8; i++) {
        int r = ldr + i * 16;
        float4 v = *(const float4*)(Q + (size_t)(row0 + r) * HDz + ldc4);
        SQ(r, ldc4 + 0) = tfr(v.x); SQ(r, ldc4 + 1) = tfr(v.y);
        SQ(r, ldc4 + 2) = tfr(v.z); SQ(r, ldc4 + 3) = tfr(v.w);
    }
    if (tid < 128) { sMrun[tid] = -1e30f; sLrun[tid] = 0.f; }

    // ================= pass 1: online max / sum =================
    for (int ct = 0; ct <= rb; ct++) {
        int col0 = ct * 128;
        #pragma unroll
        for (int i = 0; i < 8; i++) {
            int r = ldr + i * 16;
            float4 kk = *(const float4*)(Kd + (size_t)(col0 + r) * HDz + ldc4);
            SK(ldc4 + 0, r) = tfr(kk.x); SK(ldc4 + 1, r) = tfr(kk.y);
            SK(ldc4 + 2, r) = tfr(kk.z); SK(ldc4 + 3, r) = tfr(kk.w);
        }
        __syncthreads();

        float acc[16][4];
        #pragma unroll
        for (int i = 0; i < 16; i++)
            #pragma unroll
            for (int j = 0; j < 4; j++) acc[i][j] = 0.f;
        #pragma unroll
        for (int ks = 0; ks < 8; ks++) {
            int k = ks * 8;
            uint32_t afr[4][4], bfr[4][2];
            #pragma unroll
            for (int mi = 0; mi < 4; mi++) {
                int r = wm + mi * 16 + g;
                afr[mi][0] = __float_as_uint(SQ(r, k + t));
                afr[mi][1] = __float_as_uint(SQ(r + 8, k + t));
                afr[mi][2] = __float_as_uint(SQ(r, k + t + 4));
                afr[mi][3] = __float_as_uint(SQ(r + 8, k + t + 4));
            }
            #pragma unroll
            for (int ni = 0; ni < 4; ni++) {
                int c = wn + ni * 8 + g;
                bfr[ni][0] = __float_as_uint(SK(k + t, c));
                bfr[ni][1] = __float_as_uint(SK(k + t + 4, c));
            }
            #pragma unroll
            for (int mi = 0; mi < 4; mi++)
                #pragma unroll
                for (int ni = 0; ni < 4; ni++)
                    mma_tf32(acc[mi * 4 + ni], afr[mi], bfr[ni]);
        }
        #pragma unroll
        for (int i = 0; i < 16; i++)
            #pragma unroll
            for (int j = 0; j < 4; j++) acc[i][j] *= 0.125f;
        if (ct == rb) {
            #pragma unroll
            for (int mi = 0; mi < 4; mi++)
                #pragma unroll
                for (int ni = 0; ni < 4; ni++) {
                    int rl0 = wm + mi * 16 + g, rl1 = rl0 + 8;
                    int cl = wn + ni * 8 + t * 2;
                    if (cl     > rl0) acc[mi * 4 + ni][0] = -1e30f;
                    if (cl + 1 > rl0) acc[mi * 4 + ni][1] = -1e30f;
                    if (cl     > rl1) acc[mi * 4 + ni][2] = -1e30f;
                    if (cl + 1 > rl1) acc[mi * 4 + ni][3] = -1e30f;
                }
        }
        // fragment row-max, reduce across quad (t) then across wn warps
        float fm[8];
        #pragma unroll
        for (int mi = 0; mi < 4; mi++) {
            float m0 = -1e30f, m1 = -1e30f;
            #pragma unroll
            for (int ni = 0; ni < 4; ni++) {
                m0 = fmaxf(m0, fmaxf(acc[mi * 4 + ni][0], acc[mi * 4 + ni][1]));
                m1 = fmaxf(m1, fmaxf(acc[mi * 4 + ni][2], acc[mi * 4 + ni][3]));
            }
            fm[mi * 2] = m0; fm[mi * 2 + 1] = m1;
        }
        #pragma unroll
        for (int i = 0; i < 8; i++) {
            fm[i] = fmaxf(fm[i], __shfl_xor_sync(0xffffffffu, fm[i], 1));
            fm[i] = fmaxf(fm[i], __shfl_xor_sync(0xffffffffu, fm[i], 2));
        }
        if (t == 0) {
            #pragma unroll
            for (int mi = 0; mi < 4; mi++) {
                sRedM[wnI * 128 + wm + mi * 16 + g]     = fm[mi * 2];
                sRedM[wnI * 128 + wm + mi * 16 + 8 + g] = fm[mi * 2 + 1];
            }
        }
        __syncthreads();
        if (tid < 128) {
            float mt = fmaxf(fmaxf(sRedM[tid], sRedM[128 + tid]),
                             fmaxf(sRedM[256 + tid], sRedM[384 + tid]));
            float mo = sMrun[tid];
            float mn = fmaxf(mo, mt);
            sScl[tid] = fexp(mo - mn);
            sMrun[tid] = mn;
        }
        __syncthreads();
        float fs[8];
        #pragma unroll
        for (int mi = 0; mi < 4; mi++) {
            int rl0 = wm + mi * 16 + g, rl1 = rl0 + 8;
            float M0 = sMrun[rl0], M1 = sMrun[rl1];
            float s0 = 0.f, s1 = 0.f;
            #pragma unroll
            for (int ni = 0; ni < 4; ni++) {
                s0 += fexp(acc[mi * 4 + ni][0] - M0) + fexp(acc[mi * 4 + ni][1] - M0);
                s1 += fexp(acc[mi * 4 + ni][2] - M1) + fexp(acc[mi * 4 + ni][3] - M1);
            }
            fs[mi * 2] = s0; fs[mi * 2 + 1] = s1;
        }
        #pragma unroll
        for (int i = 0; i < 8; i++) {
            fs[i] += __shfl_xor_sync(0xffffffffu, fs[i], 1);
            fs[i] += __shfl_xor_sync(0xffffffffu, fs[i], 2);
        }
        if (t == 0) {
            #pragma unroll
            for (int mi = 0; mi < 4; mi++) {
                sRedL[wnI * 128 + wm + mi * 16 + g]     = fs[mi * 2];
                sRedL[wnI * 128 + wm + mi * 16 + 8 + g] = fs[mi * 2 + 1];
            }
        }
        __syncthreads();
        if (tid < 128) {
            float ts = sRedL[tid] + sRedL[128 + tid] + sRedL[256 + tid] + sRedL[384 + tid];
            sLrun[tid] = sLrun[tid] * sScl[tid] + ts;
        }
        __syncthreads();
    }
    if (tid < 128) sLinv[tid] = 1.0f / sLrun[tid];

    // ================= pass 2: write w + accumulate A ===========
    float acc2[8][4];
    #pragma unroll
    for (int i = 0; i < 8; i++)
        #pragma unroll
        for (int j = 0; j < 4; j++) acc2[i][j] = 0.f;
    int wm2 = wid * 16;

    for (int ct = 0; ct <= rb; ct++) {
        int col0 = ct * 128;
        __syncthreads();   // protect sK/sV/sP from previous iteration reads
        #pragma unroll
        for (int i = 0; i < 8; i++) {
            int r = ldr + i * 16;
            float4 kk = *(const float4*)(Kd + (size_t)(col0 + r) * HDz + ldc4);
            SK(ldc4 + 0, r) = tfr(kk.x); SK(ldc4 + 1, r) = tfr(kk.y);
            SK(ldc4 + 2, r) = tfr(kk.z); SK(ldc4 + 3, r) = tfr(kk.w);
            float4 vv = *(const float4*)(Vd + (size_t)(col0 + r) * HDz + ldc4);
            SV(r, ldc4 + 0) = tfr(vv.x); SV(r, ldc4 + 1) = tfr(vv.y);
            SV(r, ldc4 + 2) = tfr(vv.z); SV(r, ldc4 + 3) = tfr(vv.w);
        }
        __syncthreads();

        float acc[16][4];
        #pragma unroll
        for (int i = 0; i < 16; i++)
            #pragma unroll
            for (int j = 0; j < 4; j++) acc[i][j] = 0.f;
        #pragma unroll
        for (int ks = 0; ks < 8; ks++) {
            int k = ks * 8;
            uint32_t afr[4][4], bfr[4][2];
            #pragma unroll
            for (int mi = 0; mi < 4; mi++) {
                int r = wm + mi * 16 + g;
                afr[mi][0] = __float_as_uint(SQ(r, k + t));
                afr[mi][1] = __float_as_uint(SQ(r + 8, k + t));
                afr[mi][2] = __float_as_uint(SQ(r, k + t + 4));
                afr[mi][3] = __float_as_uint(SQ(r + 8, k + t + 4));
            }
            #pragma unroll
            for (int ni = 0; ni < 4; ni++) {
                int c = wn + ni * 8 + g;
                bfr[ni][0] = __float_as_uint(SK(k + t, c));
                bfr[ni][1] = __float_as_uint(SK(k + t + 4, c));
            }
            #pragma unroll
            for (int mi = 0; mi < 4; mi++)
                #pragma unroll
                for (int ni = 0; ni < 4; ni++)
                    mma_tf32(acc[mi * 4 + ni], afr[mi], bfr[ni]);
        }

        bool dg = (ct == rb);
        #pragma unroll
        for (int mi = 0; mi < 4; mi++) {
            #pragma unroll
            for (int ni = 0; ni < 4; ni++) {
                int rl0 = wm + mi * 16 + g, rl1 = rl0 + 8;
                int cl = wn + ni * 8 + t * 2;
                float M0 = sMrun[rl0], L0 = sLinv[rl0];
                float M1 = sMrun[rl1], L1 = sLinv[rl1];
                float p0 = fexp(fmaf(acc[mi * 4 + ni][0], 0.125f, -M0)) * L0;
                float p1 = fexp(fmaf(acc[mi * 4 + ni][1], 0.125f, -M0)) * L0;
                float p2 = fexp(fmaf(acc[mi * 4 + ni][2], 0.125f, -M1)) * L1;
                float p3 = fexp(fmaf(acc[mi * 4 + ni][3], 0.125f, -M1)) * L1;
                if (dg) {
                    if (cl     > rl0) p0 = 0.f;
                    if (cl + 1 > rl0) p1 = 0.f;
                    if (cl     > rl1) p2 = 0.f;
                    if (cl + 1 > rl1) p3 = 0.f;
                }
                *(float2*)(W + (size_t)(row0 + rl0) * Sz + col0 + cl) = make_float2(p0, p1);
                *(float2*)(W + (size_t)(row0 + rl1) * Sz + col0 + cl) = make_float2(p2, p3);
                SP(rl0, cl)     = tfr(p0);
                SP(rl0, cl + 1) = tfr(p1);
                SP(rl1, cl)     = tfr(p2);
                SP(rl1, cl + 1) = tfr(p3);
            }
        }
        __syncthreads();

        // A += P @ V   (P 128x128 from smem, V 128x64 from smem)
        #pragma unroll
        for (int ks = 0; ks < 16; ks++) {
            int k = ks * 8;
            uint32_t afr[4];
            afr[0] = __float_as_uint(SP(wm2 + g, k + t));
            afr[1] = __float_as_uint(SP(wm2 + 8 + g, k + t));
            afr[2] = __float_as_uint(SP(wm2 + g, k + t + 4));
            afr[3] = __float_as_uint(SP(wm2 + 8 + g, k + t + 4));
            #pragma unroll
            for (int ni = 0; ni < 8; ni++) {
                uint32_t bfr[2];
                bfr[0] = __float_as_uint(SV(k + t, ni * 8 + g));
                bfr[1] = __float_as_uint(SV(k + t + 4, ni * 8 + g));
                mma_tf32(acc2[ni], afr, bfr);
            }
        }
    }

    // write A tile to g_a [B,S,D]
    float* A = a + ((size_t)b * Sz + row0) * Dz + h * HDz;
    #pragma unroll
    for (int ni = 0; ni < 8; ni++) {
        int r0 = wm2 + g, c = ni * 8 + t * 2;
        *(float2*)(A + (size_t)r0 * Dz + c)       = make_float2(acc2[ni][0], acc2[ni][1]);
        *(float2*)(A + (size_t)(r0 + 8) * Dz + c) = make_float2(acc2[ni][2], acc2[ni][3]);
    }

    // zero-fill above-diagonal tiles of w for these rows
    int cstart = row0 + 128;
    if (cstart < Sz) {
        int w4 = (Sz - cstart) >> 2;
        float4 z4 = make_float4(0.f, 0.f, 0.f, 0.f);
        for (int i = tid; i < 128 * w4; i += 256) {
            int r = i / w4;
            int cc = (i - r * w4) * 4 + cstart;
            *(float4*)(W + (size_t)(row0 + r) * Sz + cc) = z4;
        }
    }
}

// ---------------- host ------------------------------------------------------
extern "C" void kernel_launch(void* const* d_in, const int* in_sizes, int n_in,
                              void* d_out, int out_size) {
    const float* x       = (const float*)d_in[0];
    const float* qkv_w   = (const float*)d_in[1];
    const float* qkv_b   = (const float*)d_in[2];
    const float* merge_w = (const float*)d_in[3];
    const float* merge_b = (const float*)d_in[4];
    const float* mlp1_w  = (const float*)d_in[5];
    const float* mlp1_b  = (const float*)d_in[6];
    const float* mlp2_w  = (const float*)d_in[7];
    const float* mlp2_b  = (const float*)d_in[8];
    const float* n1_g    = (const float*)d_in[9];
    const float* n1_b    = (const float*)d_in[10];
    const float* n2_g    = (const float*)d_in[11];
    const float* n2_b    = (const float*)d_in[12];

    float *ln, *q, *a, *xa, *h1;
    cudaGetSymbolAddress((void**)&ln, g_ln);
    cudaGetSymbolAddress((void**)&q,  g_q);
    cudaGetSymbolAddress((void**)&a,  g_a);
    cudaGetSymbolAddress((void**)&xa, g_xa);
    cudaGetSymbolAddress((void**)&h1, g_h1);

    float* out     = (float*)d_out;
    float* xm      = out;                                      // [B,S,D]
    float* present = out + (size_t)Bz * Sz * Dz;               // [B,2,H,S,hd]
    float* w       = present + (size_t)Bz * 2 * Hz * Sz * HDz; // [B,H,S,S]

    const int M = Bz * Sz;   // 4096
    const int attnSmem = (128 * 68 + 64 * 133 + 128 * 68 + 128 * 132 + 128 * 4 + 512 * 2) * 4;
    static int attrSet = 0;
    if (!attrSet) {
        cudaFuncSetAttribute(attn_fused, cudaFuncAttributeMaxDynamicSharedMemorySize, attnSmem);
        attrSet = 1;
    }

    // 1) ln1
    layernorm_k<<<M, 256>>>(x, n1_g, n1_b, ln);
    // 2) qkv gemm, epilogue scatters directly to q scratch + present (output)
    tf32gemm<3><<<dim3(3 * Dz / 128, M / 128), 256>>>(ln, qkv_w, qkv_b, nullptr, nullptr,
                                                      q, present, M, 3 * Dz, Dz, Dz, 3 * Dz, 3 * Dz);
    // 3) fused attention: scores + softmax + A = P@V, writes w exactly once
    attn_fused<<<dim3(1, Sz / 128, Bz * Hz), 256, attnSmem>>>(q, present, w, a);
    // 4) merge gemm + residual -> xa
    tf32gemm<1><<<dim3(Dz / 128, M / 128), 256>>>(a, merge_w, merge_b, x, xa, nullptr, nullptr,
                                                  M, Dz, Dz, Dz, Dz, Dz);
    // 5) ln2
    layernorm_k<<<M, 256>>>(xa, n2_g, n2_b, ln);
    // 6) mlp1 + gelu
    tf32gemm<2><<<dim3(4 * Dz / 128, M / 128), 256>>>(ln, mlp1_w, mlp1_b, nullptr, h1, nullptr, nullptr,
                                                      M, 4 * Dz, Dz, Dz, 4 * Dz, 4 * Dz);
    // 7) mlp2 + residual -> xm (output)
    tf32gemm<1><<<dim3(Dz / 128, M / 128), 256>>>(h1, mlp2_w, mlp2_b, xa, xm, nullptr, nullptr,
                                                  M, Dz, 4 * Dz, 4 * Dz, Dz, Dz);
}